// round 2
// baseline (speedup 1.0000x reference)
#include <cuda_runtime.h>
#include <cuda_bf16.h>
#include <cstdint>
#include <cstring>

#define DEVINL __device__ __forceinline__
using bf16 = __nv_bfloat16;

// ---------------- problem sizes ----------------
constexpr int M_TOK = 8192;        // B*S
constexpr int DIM   = 2048;        // D
constexpr int NEXP  = 64;
constexpr int N1 = 4096;           // E*R   (gemm1 N == gemm2 K)
constexpr int K1 = DIM;            // 2048
constexpr int N2 = DIM;            // 2048
constexpr int K2 = N1;             // 4096

// ---------------- tiling ----------------
constexpr int TM = 256, TN = 128, KC = 64, STAGES = 2;
constexpr int A_TILE = TM * 128;               // bytes per A part (hi or lo): 32 KB
constexpr int B_TILE = TN * 128;               // 16 KB
constexpr int STAGE_BYTES = 2 * A_TILE + 2 * B_TILE;   // 96 KB
constexpr int SMEM_BYTES  = STAGES * STAGE_BYTES + 1024;

// ---------------- device scratch ----------------
__device__ __align__(16) bf16 g_x_hi [M_TOK * K1];
__device__ __align__(16) bf16 g_x_lo [M_TOK * K1];
__device__ __align__(16) bf16 g_wu_hi[N1 * K1];
__device__ __align__(16) bf16 g_wu_lo[N1 * K1];
__device__ __align__(16) bf16 g_wd_hi[N2 * K2];
__device__ __align__(16) bf16 g_wd_lo[N2 * K2];
__device__ __align__(16) bf16 g_h_hi [M_TOK * K2];
__device__ __align__(16) bf16 g_h_lo [M_TOK * K2];

// ---------------- helpers ----------------
DEVINL uint32_t smem_u32(const void* p) {
    uint32_t r;
    asm("{ .reg .u64 t; cvta.to.shared.u64 t, %1; cvt.u32.u64 %0, t; }"
        : "=r"(r) : "l"(p));
    return r;
}

DEVINL void cp16(uint32_t dst, const void* src) {
    asm volatile("cp.async.cg.shared.global [%0], [%1], 16;"
                 :: "r"(dst), "l"(src) : "memory");
}
DEVINL void cp_commit() { asm volatile("cp.async.commit_group;" ::: "memory"); }
template <int N> DEVINL void cp_wait() {
    asm volatile("cp.async.wait_group %0;" :: "n"(N) : "memory");
}

DEVINL void ldsm4(uint32_t (&r)[4], uint32_t addr) {
    asm volatile("ldmatrix.sync.aligned.m8n8.x4.shared.b16 {%0,%1,%2,%3}, [%4];"
                 : "=r"(r[0]), "=r"(r[1]), "=r"(r[2]), "=r"(r[3]) : "r"(addr));
}

DEVINL void mma16816(float (&c)[4], const uint32_t (&a)[4], const uint32_t* b) {
    asm volatile(
        "mma.sync.aligned.m16n8k16.row.col.f32.bf16.bf16.f32 "
        "{%0,%1,%2,%3}, {%4,%5,%6,%7}, {%8,%9}, {%0,%1,%2,%3};"
        : "+f"(c[0]), "+f"(c[1]), "+f"(c[2]), "+f"(c[3])
        : "r"(a[0]), "r"(a[1]), "r"(a[2]), "r"(a[3]), "r"(b[0]), "r"(b[1]));
}

DEVINL uint32_t pk2(bf16 a, bf16 b) {
    __nv_bfloat162 t = __halves2bfloat162(a, b);
    uint32_t u;
    memcpy(&u, &t, 4);
    return u;
}

// ---------------- split: fp32 -> (hi, lo) bf16 ----------------
DEVINL void split4(float4 v, bf16* hi, bf16* lo, int i) {
    float f[4] = {v.x, v.y, v.z, v.w};
    bf16 h[4], l[4];
#pragma unroll
    for (int j = 0; j < 4; j++) {
        h[j] = __float2bfloat16_rn(f[j]);
        l[j] = __float2bfloat16_rn(f[j] - __bfloat162float(h[j]));
    }
    uint2 uh, ul;
    uh.x = pk2(h[0], h[1]); uh.y = pk2(h[2], h[3]);
    ul.x = pk2(l[0], l[1]); ul.y = pk2(l[2], l[3]);
    reinterpret_cast<uint2*>(hi)[i] = uh;
    reinterpret_cast<uint2*>(lo)[i] = ul;
}

__global__ void split_kernel(const float4* __restrict__ x,
                             const float4* __restrict__ wu,
                             const float4* __restrict__ wd) {
    const int X4  = M_TOK * K1 / 4;
    const int WU4 = N1 * K1 / 4;
    const int WD4 = N2 * K2 / 4;
    const int stride = gridDim.x * blockDim.x;
    const int t0 = blockIdx.x * blockDim.x + threadIdx.x;
    for (int i = t0; i < X4;  i += stride) split4(x[i],  g_x_hi,  g_x_lo,  i);
    for (int i = t0; i < WU4; i += stride) split4(wu[i], g_wu_hi, g_wu_lo, i);
    for (int i = t0; i < WD4; i += stride) split4(wd[i], g_wd_hi, g_wd_lo, i);
}

// ---------------- tile loader (SW128 swizzle) ----------------
template <int ROWS>
DEVINL void load_tile(uint32_t sub, const bf16* __restrict__ src,
                      int row0, int k0, int KDIM, int tid) {
    constexpr int ITERS = ROWS * 8 / 256;   // 16B segments / 256 threads
#pragma unroll
    for (int j = 0; j < ITERS; j++) {
        const int idx = tid + j * 256;
        const int rr = idx >> 3;
        const int ss = idx & 7;
        const uint32_t off = (uint32_t)(rr * 128 + ss * 16);
        const uint32_t dst = sub + (off ^ ((off >> 3) & 0x70));
        cp16(dst, src + (size_t)(row0 + rr) * KDIM + (k0 + ss * 8));
    }
}

DEVINL void load_chunk(uint32_t sb, int k0, int tid,
                       const bf16* Ah, const bf16* Al,
                       const bf16* Bh, const bf16* Bl,
                       int m0, int n0, int KDIM) {
    load_tile<TM>(sb,                      Ah, m0, k0, KDIM, tid);
    load_tile<TM>(sb + A_TILE,             Al, m0, k0, KDIM, tid);
    load_tile<TN>(sb + 2 * A_TILE,         Bh, n0, k0, KDIM, tid);
    load_tile<TN>(sb + 2 * A_TILE + B_TILE, Bl, n0, k0, KDIM, tid);
    cp_commit();
}

// ---------------- per-chunk MMA (bf16x3) ----------------
DEVINL void compute_chunk(uint32_t sb, int lane, int wm, int wn,
                          float (&acc)[4][8][4]) {
    const uint32_t subAh = sb;
    const uint32_t subAl = sb + A_TILE;
    const uint32_t subBh = sb + 2 * A_TILE;
    const uint32_t subBl = sb + 2 * A_TILE + B_TILE;

    // ldmatrix lane addressing (see fragment-layout derivation)
    const int a_r0 = wm * 64 + (lane & 7) + ((lane >> 3) & 1) * 8;   // + mb*16
    const int a_k8 = (lane >> 4);                                    // k += 8*a_k8
    const int b_r0 = wn * 64 + (lane & 7) + (lane >> 4) * 8;         // + g*16
    const int b_k8 = (lane >> 3) & 1;

#pragma unroll
    for (int ks = 0; ks < KC / 16; ks++) {
        uint32_t ah[4][4], al[4][4];
#pragma unroll
        for (int mb = 0; mb < 4; mb++) {
            const int r = a_r0 + mb * 16;
            const int kk = ks * 16 + a_k8 * 8;
            const uint32_t off = (uint32_t)(r * 128) + (((uint32_t)(kk * 2)) ^ (uint32_t)((r & 7) << 4));
            ldsm4(ah[mb], subAh + off);
            ldsm4(al[mb], subAl + off);
        }
#pragma unroll
        for (int g = 0; g < 4; g++) {
            const int r = b_r0 + g * 16;
            const int kk = ks * 16 + b_k8 * 8;
            const uint32_t off = (uint32_t)(r * 128) + (((uint32_t)(kk * 2)) ^ (uint32_t)((r & 7) << 4));
            uint32_t bh[4], bl[4];
            ldsm4(bh, subBh + off);
            ldsm4(bl, subBl + off);
#pragma unroll
            for (int h = 0; h < 2; h++) {
#pragma unroll
                for (int mb = 0; mb < 4; mb++) {
                    float (&c)[4] = acc[mb][g * 2 + h];
                    mma16816(c, ah[mb], bh + 2 * h);   // hi*hi
                    mma16816(c, ah[mb], bl + 2 * h);   // hi*lo
                    mma16816(c, al[mb], bh + 2 * h);   // lo*hi
                }
            }
        }
    }
}

// ---------------- GEMM kernels ----------------
// MODE 1: X * WupT, fused silu*mask, write h (hi/lo bf16)
// MODE 2: h * WdnT, write fp32 out
template <int MODE>
__global__ void __launch_bounds__(256, 1)
gemm_kernel(const float* __restrict__ mask, float* __restrict__ out) {
    constexpr int KDIM = (MODE == 1) ? K1 : K2;
    constexpr int NC = KDIM / KC;
    const bf16 *Ah, *Al, *Bh, *Bl;
    if (MODE == 1) { Ah = g_x_hi; Al = g_x_lo; Bh = g_wu_hi; Bl = g_wu_lo; }
    else           { Ah = g_h_hi; Al = g_h_lo; Bh = g_wd_hi; Bl = g_wd_lo; }

    extern __shared__ __align__(1024) uint8_t smem_raw[];
    const uint32_t base = (smem_u32(smem_raw) + 1023u) & ~1023u;

    const int tid = threadIdx.x;
    const int lane = tid & 31;
    const int wid = tid >> 5;
    const int wm = wid >> 1;          // 0..3  (m 64-blocks)
    const int wn = wid & 1;           // 0..1  (n 64-blocks)
    const int m0 = blockIdx.y * TM;
    const int n0 = blockIdx.x * TN;

    float acc[4][8][4];
#pragma unroll
    for (int i = 0; i < 4; i++)
#pragma unroll
        for (int j = 0; j < 8; j++)
#pragma unroll
            for (int q = 0; q < 4; q++) acc[i][j][q] = 0.f;

    load_chunk(base,               0,  tid, Ah, Al, Bh, Bl, m0, n0, KDIM);
    load_chunk(base + STAGE_BYTES, KC, tid, Ah, Al, Bh, Bl, m0, n0, KDIM);

    for (int c = 0; c < NC; ++c) {
        if (c + 1 < NC) cp_wait<1>(); else cp_wait<0>();
        __syncthreads();
        compute_chunk(base + (c & 1) * STAGE_BYTES, lane, wm, wn, acc);
        __syncthreads();
        if (c + 2 < NC)
            load_chunk(base + (c & 1) * STAGE_BYTES, (c + 2) * KC,
                       tid, Ah, Al, Bh, Bl, m0, n0, KDIM);
    }

    // ---------------- epilogue ----------------
    const int mw0 = m0 + wm * 64;
    const int nw0 = n0 + wn * 64;
#pragma unroll
    for (int mb = 0; mb < 4; mb++) {
        const int r0 = mw0 + mb * 16 + (lane >> 2);
        if (MODE == 1) {
            const int e = nw0 >> 6;   // one expert per 64-wide warp n-tile
            const float mk0 = mask[(size_t)r0 * NEXP + e];
            const float mk1 = mask[(size_t)(r0 + 8) * NEXP + e];
#pragma unroll
            for (int nb = 0; nb < 8; nb++) {
                const int col = nw0 + nb * 8 + (lane & 3) * 2;
                float v[4] = {acc[mb][nb][0], acc[mb][nb][1],
                              acc[mb][nb][2], acc[mb][nb][3]};
                float hv[4];
                hv[0] = v[0] * (1.f / (1.f + __expf(-v[0]))) * mk0;
                hv[1] = v[1] * (1.f / (1.f + __expf(-v[1]))) * mk0;
                hv[2] = v[2] * (1.f / (1.f + __expf(-v[2]))) * mk1;
                hv[3] = v[3] * (1.f / (1.f + __expf(-v[3]))) * mk1;
                bf16 hb[4], lb[4];
#pragma unroll
                for (int q = 0; q < 4; q++) {
                    hb[q] = __float2bfloat16_rn(hv[q]);
                    lb[q] = __float2bfloat16_rn(hv[q] - __bfloat162float(hb[q]));
                }
                *reinterpret_cast<uint32_t*>(g_h_hi + (size_t)r0 * K2 + col)       = pk2(hb[0], hb[1]);
                *reinterpret_cast<uint32_t*>(g_h_hi + (size_t)(r0 + 8) * K2 + col) = pk2(hb[2], hb[3]);
                *reinterpret_cast<uint32_t*>(g_h_lo + (size_t)r0 * K2 + col)       = pk2(lb[0], lb[1]);
                *reinterpret_cast<uint32_t*>(g_h_lo + (size_t)(r0 + 8) * K2 + col) = pk2(lb[2], lb[3]);
            }
        } else {
#pragma unroll
            for (int nb = 0; nb < 8; nb++) {
                const int col = nw0 + nb * 8 + (lane & 3) * 2;
                *reinterpret_cast<float2*>(out + (size_t)r0 * N2 + col) =
                    make_float2(acc[mb][nb][0], acc[mb][nb][1]);
                *reinterpret_cast<float2*>(out + (size_t)(r0 + 8) * N2 + col) =
                    make_float2(acc[mb][nb][2], acc[mb][nb][3]);
            }
        }
    }
}

// ---------------- launch ----------------
extern "C" void kernel_launch(void* const* d_in, const int* in_sizes, int n_in,
                              void* d_out, int out_size) {
    const float* x    = (const float*)d_in[0];   // [8192, 2048]
    const float* mask = (const float*)d_in[1];   // [8192, 64]
    const float* wu   = (const float*)d_in[2];   // [4096, 2048]
    const float* wd   = (const float*)d_in[3];   // [2048, 4096]
    float* out = (float*)d_out;

    cudaFuncSetAttribute(gemm_kernel<1>, cudaFuncAttributeMaxDynamicSharedMemorySize, SMEM_BYTES);
    cudaFuncSetAttribute(gemm_kernel<2>, cudaFuncAttributeMaxDynamicSharedMemorySize, SMEM_BYTES);

    split_kernel<<<1024, 256>>>((const float4*)x, (const float4*)wu, (const float4*)wd);
    gemm_kernel<1><<<dim3(N1 / TN, M_TOK / TM), 256, SMEM_BYTES>>>(mask, nullptr);
    gemm_kernel<2><<<dim3(N2 / TN, M_TOK / TM), 256, SMEM_BYTES>>>(nullptr, out);
}

// round 3
// speedup vs baseline: 2.4538x; 2.4538x over previous
#include <cuda_runtime.h>
#include <cuda_fp16.h>
#include <cstdint>
#include <cstring>

#define DEVINL __device__ __forceinline__

// ---------------- problem sizes ----------------
constexpr int M_TOK = 8192;        // B*S
constexpr int DIM   = 2048;        // D
constexpr int NEXP  = 64;
constexpr int N1 = 4096;           // E*R   (gemm1 N == gemm2 K)
constexpr int K1 = DIM;            // 2048
constexpr int N2 = DIM;            // 2048
constexpr int K2 = N1;             // 4096

// ---------------- tiling ----------------
constexpr int TM = 256, TN = 128, KC = 64, STAGES = 4;
constexpr int A_TILE = TM * KC * 2;            // 32 KB
constexpr int B_TILE = TN * KC * 2;            // 16 KB
constexpr int STAGE_BYTES = A_TILE + B_TILE;   // 48 KB
constexpr int SMEM_BYTES  = STAGES * STAGE_BYTES + 1024;   // 192 KB + pad

// ---------------- device scratch (fp16 operands) ----------------
__device__ __align__(16) __half g_x [M_TOK * K1];
__device__ __align__(16) __half g_wu[N1 * K1];
__device__ __align__(16) __half g_wd[N2 * K2];
__device__ __align__(16) __half g_h [M_TOK * K2];

// ---------------- helpers ----------------
DEVINL uint32_t smem_u32(const void* p) {
    uint32_t r;
    asm("{ .reg .u64 t; cvta.to.shared.u64 t, %1; cvt.u32.u64 %0, t; }"
        : "=r"(r) : "l"(p));
    return r;
}

DEVINL void cp16(uint32_t dst, const void* src) {
    asm volatile("cp.async.cg.shared.global [%0], [%1], 16;"
                 :: "r"(dst), "l"(src) : "memory");
}
DEVINL void cp_commit() { asm volatile("cp.async.commit_group;" ::: "memory"); }
template <int N> DEVINL void cp_wait() {
    asm volatile("cp.async.wait_group %0;" :: "n"(N) : "memory");
}

DEVINL void ldsm4(uint32_t (&r)[4], uint32_t addr) {
    asm volatile("ldmatrix.sync.aligned.m8n8.x4.shared.b16 {%0,%1,%2,%3}, [%4];"
                 : "=r"(r[0]), "=r"(r[1]), "=r"(r[2]), "=r"(r[3]) : "r"(addr));
}

DEVINL void mma16816(float (&c)[4], const uint32_t (&a)[4], const uint32_t* b) {
    asm volatile(
        "mma.sync.aligned.m16n8k16.row.col.f32.f16.f16.f32 "
        "{%0,%1,%2,%3}, {%4,%5,%6,%7}, {%8,%9}, {%0,%1,%2,%3};"
        : "+f"(c[0]), "+f"(c[1]), "+f"(c[2]), "+f"(c[3])
        : "r"(a[0]), "r"(a[1]), "r"(a[2]), "r"(a[3]), "r"(b[0]), "r"(b[1]));
}

DEVINL uint32_t pk2h(__half a, __half b) {
    __half2 t = __halves2half2(a, b);
    uint32_t u;
    memcpy(&u, &t, 4);
    return u;
}

// ---------------- convert: fp32 -> fp16 ----------------
DEVINL void cvt4(float4 v, __half* dst, int i) {
    uint2 u;
    u.x = pk2h(__float2half_rn(v.x), __float2half_rn(v.y));
    u.y = pk2h(__float2half_rn(v.z), __float2half_rn(v.w));
    reinterpret_cast<uint2*>(dst)[i] = u;
}

__global__ void convert_kernel(const float4* __restrict__ x,
                               const float4* __restrict__ wu,
                               const float4* __restrict__ wd) {
    const int X4  = M_TOK * K1 / 4;
    const int WU4 = N1 * K1 / 4;
    const int WD4 = N2 * K2 / 4;
    const int stride = gridDim.x * blockDim.x;
    const int t0 = blockIdx.x * blockDim.x + threadIdx.x;
    for (int i = t0; i < X4;  i += stride) cvt4(x[i],  g_x,  i);
    for (int i = t0; i < WU4; i += stride) cvt4(wu[i], g_wu, i);
    for (int i = t0; i < WD4; i += stride) cvt4(wd[i], g_wd, i);
}

// ---------------- tile loader (SW128 swizzle) ----------------
template <int ROWS>
DEVINL void load_tile(uint32_t sub, const __half* __restrict__ src,
                      int row0, int k0, int KDIM, int tid) {
    constexpr int ITERS = ROWS * 8 / 256;
#pragma unroll
    for (int j = 0; j < ITERS; j++) {
        const int idx = tid + j * 256;
        const int rr = idx >> 3;
        const int ss = idx & 7;
        const uint32_t off = (uint32_t)(rr * 128 + ss * 16);
        const uint32_t dst = sub + (off ^ ((off >> 3) & 0x70));
        cp16(dst, src + (size_t)(row0 + rr) * KDIM + (k0 + ss * 8));
    }
}

DEVINL void load_chunk(uint32_t sb, int k0, int tid,
                       const __half* A, const __half* B,
                       int m0, int n0, int KDIM) {
    load_tile<TM>(sb,          A, m0, k0, KDIM, tid);
    load_tile<TN>(sb + A_TILE, B, n0, k0, KDIM, tid);
    cp_commit();
}

// ---------------- per-chunk MMA ----------------
DEVINL void compute_chunk(uint32_t sb, int lane, int wm, int wn,
                          float (&acc)[4][8][4]) {
    const uint32_t subA = sb;
    const uint32_t subB = sb + A_TILE;

    const int a_r0 = wm * 64 + (lane & 7) + ((lane >> 3) & 1) * 8;   // + mb*16
    const int a_k8 = (lane >> 4);
    const int b_r0 = wn * 64 + (lane & 7) + (lane >> 4) * 8;         // + g*16
    const int b_k8 = (lane >> 3) & 1;

#pragma unroll
    for (int ks = 0; ks < KC / 16; ks++) {
        uint32_t a[4][4];
#pragma unroll
        for (int mb = 0; mb < 4; mb++) {
            const int r = a_r0 + mb * 16;
            const int kk = ks * 16 + a_k8 * 8;
            const uint32_t off = (uint32_t)(r * 128) + (((uint32_t)(kk * 2)) ^ (uint32_t)((r & 7) << 4));
            ldsm4(a[mb], subA + off);
        }
#pragma unroll
        for (int g = 0; g < 4; g++) {
            const int r = b_r0 + g * 16;
            const int kk = ks * 16 + b_k8 * 8;
            const uint32_t off = (uint32_t)(r * 128) + (((uint32_t)(kk * 2)) ^ (uint32_t)((r & 7) << 4));
            uint32_t b[4];
            ldsm4(b, subB + off);
#pragma unroll
            for (int h = 0; h < 2; h++)
#pragma unroll
                for (int mb = 0; mb < 4; mb++)
                    mma16816(acc[mb][g * 2 + h], a[mb], b + 2 * h);
        }
    }
}

// ---------------- GEMM kernels ----------------
// MODE 1: X * WupT, fused silu*mask -> h (fp16)
// MODE 2: h * WdnT -> out fp32
template <int MODE>
__global__ void __launch_bounds__(256, 1)
gemm_kernel(const float* __restrict__ mask, float* __restrict__ out) {
    constexpr int KDIM = (MODE == 1) ? K1 : K2;
    constexpr int NC = KDIM / KC;
    const __half* A = (MODE == 1) ? g_x  : g_h;
    const __half* B = (MODE == 1) ? g_wu : g_wd;

    extern __shared__ __align__(1024) uint8_t smem_raw[];
    const uint32_t base = (smem_u32(smem_raw) + 1023u) & ~1023u;

    const int tid = threadIdx.x;
    const int lane = tid & 31;
    const int wid = tid >> 5;
    const int wm = wid >> 1;
    const int wn = wid & 1;
    const int m0 = blockIdx.y * TM;
    const int n0 = blockIdx.x * TN;

    float acc[4][8][4];
#pragma unroll
    for (int i = 0; i < 4; i++)
#pragma unroll
        for (int j = 0; j < 8; j++)
#pragma unroll
            for (int q = 0; q < 4; q++) acc[i][j][q] = 0.f;

    // prologue: stages 0..2
#pragma unroll
    for (int s = 0; s < 3; s++)
        load_chunk(base + s * STAGE_BYTES, s * KC, tid, A, B, m0, n0, KDIM);

    for (int c = 0; c < NC; ++c) {
        if (c <= NC - 3)      cp_wait<2>();
        else if (c == NC - 2) cp_wait<1>();
        else                  cp_wait<0>();
        __syncthreads();   // all warps done with chunk c-1 (stage (c+3)%4)

        if (c + 3 < NC)
            load_chunk(base + ((c + 3) % STAGES) * STAGE_BYTES, (c + 3) * KC,
                       tid, A, B, m0, n0, KDIM);

        compute_chunk(base + (c % STAGES) * STAGE_BYTES, lane, wm, wn, acc);
    }

    // ---------------- epilogue ----------------
    const int mw0 = m0 + wm * 64;
    const int nw0 = n0 + wn * 64;
#pragma unroll
    for (int mb = 0; mb < 4; mb++) {
        const int r0 = mw0 + mb * 16 + (lane >> 2);
        if (MODE == 1) {
            const int e = nw0 >> 6;   // one expert per 64-wide warp n-tile
            const float mk0 = mask[(size_t)r0 * NEXP + e];
            const float mk1 = mask[(size_t)(r0 + 8) * NEXP + e];
#pragma unroll
            for (int nb = 0; nb < 8; nb++) {
                const int col = nw0 + nb * 8 + (lane & 3) * 2;
                float v[4] = {acc[mb][nb][0], acc[mb][nb][1],
                              acc[mb][nb][2], acc[mb][nb][3]};
                float hv[4];
                hv[0] = v[0] * (1.f / (1.f + __expf(-v[0]))) * mk0;
                hv[1] = v[1] * (1.f / (1.f + __expf(-v[1]))) * mk0;
                hv[2] = v[2] * (1.f / (1.f + __expf(-v[2]))) * mk1;
                hv[3] = v[3] * (1.f / (1.f + __expf(-v[3]))) * mk1;
                *reinterpret_cast<uint32_t*>(g_h + (size_t)r0 * K2 + col) =
                    pk2h(__float2half_rn(hv[0]), __float2half_rn(hv[1]));
                *reinterpret_cast<uint32_t*>(g_h + (size_t)(r0 + 8) * K2 + col) =
                    pk2h(__float2half_rn(hv[2]), __float2half_rn(hv[3]));
            }
        } else {
#pragma unroll
            for (int nb = 0; nb < 8; nb++) {
                const int col = nw0 + nb * 8 + (lane & 3) * 2;
                *reinterpret_cast<float2*>(out + (size_t)r0 * N2 + col) =
                    make_float2(acc[mb][nb][0], acc[mb][nb][1]);
                *reinterpret_cast<float2*>(out + (size_t)(r0 + 8) * N2 + col) =
                    make_float2(acc[mb][nb][2], acc[mb][nb][3]);
            }
        }
    }
}

// ---------------- launch ----------------
extern "C" void kernel_launch(void* const* d_in, const int* in_sizes, int n_in,
                              void* d_out, int out_size) {
    const float* x    = (const float*)d_in[0];   // [8192, 2048]
    const float* mask = (const float*)d_in[1];   // [8192, 64]
    const float* wu   = (const float*)d_in[2];   // [4096, 2048]
    const float* wd   = (const float*)d_in[3];   // [2048, 4096]
    float* out = (float*)d_out;

    cudaFuncSetAttribute(gemm_kernel<1>, cudaFuncAttributeMaxDynamicSharedMemorySize, SMEM_BYTES);
    cudaFuncSetAttribute(gemm_kernel<2>, cudaFuncAttributeMaxDynamicSharedMemorySize, SMEM_BYTES);

    convert_kernel<<<1024, 256>>>((const float4*)x, (const float4*)wu, (const float4*)wd);
    gemm_kernel<1><<<dim3(N1 / TN, M_TOK / TM), 256, SMEM_BYTES>>>(mask, nullptr);
    gemm_kernel<2><<<dim3(N2 / TN, M_TOK / TM), 256, SMEM_BYTES>>>(nullptr, out);
}

// round 4
// speedup vs baseline: 2.7889x; 1.1365x over previous
#include <cuda_runtime.h>
#include <cuda_fp16.h>
#include <cstdint>
#include <cstring>

#define DEVINL __device__ __forceinline__

// ---------------- problem sizes ----------------
constexpr int M_TOK = 8192;        // B*S
constexpr int DIM   = 2048;        // D
constexpr int NEXP  = 64;
constexpr int N1 = 4096;           // E*R   (gemm1 N == gemm2 K)
constexpr int K1 = DIM;            // 2048
constexpr int N2 = DIM;            // 2048
constexpr int K2 = N1;             // 4096

// ---------------- tiling ----------------
constexpr int TM = 128, TN = 128, KC = 64, STAGES = 3;
constexpr int A_TILE = TM * KC * 2;            // 16 KB
constexpr int B_TILE = TN * KC * 2;            // 16 KB
constexpr int STAGE_BYTES = A_TILE + B_TILE;   // 32 KB
constexpr int SMEM_BYTES  = STAGES * STAGE_BYTES + 1024;   // 97 KB

// ---------------- device scratch (fp16 operands) ----------------
__device__ __align__(16) __half g_x [M_TOK * K1];
__device__ __align__(16) __half g_wu[N1 * K1];
__device__ __align__(16) __half g_wd[N2 * K2];
__device__ __align__(16) __half g_h [M_TOK * K2];

// ---------------- helpers ----------------
DEVINL uint32_t smem_u32(const void* p) {
    uint32_t r;
    asm("{ .reg .u64 t; cvta.to.shared.u64 t, %1; cvt.u32.u64 %0, t; }"
        : "=r"(r) : "l"(p));
    return r;
}

DEVINL void cp16(uint32_t dst, const void* src) {
    asm volatile("cp.async.cg.shared.global [%0], [%1], 16;"
                 :: "r"(dst), "l"(src) : "memory");
}
DEVINL void cp_commit() { asm volatile("cp.async.commit_group;" ::: "memory"); }
template <int N> DEVINL void cp_wait() {
    asm volatile("cp.async.wait_group %0;" :: "n"(N) : "memory");
}

DEVINL void ldsm4(uint32_t (&r)[4], uint32_t addr) {
    asm volatile("ldmatrix.sync.aligned.m8n8.x4.shared.b16 {%0,%1,%2,%3}, [%4];"
                 : "=r"(r[0]), "=r"(r[1]), "=r"(r[2]), "=r"(r[3]) : "r"(addr));
}

DEVINL void mma16816(float (&c)[4], const uint32_t (&a)[4], const uint32_t* b) {
    asm volatile(
        "mma.sync.aligned.m16n8k16.row.col.f32.f16.f16.f32 "
        "{%0,%1,%2,%3}, {%4,%5,%6,%7}, {%8,%9}, {%0,%1,%2,%3};"
        : "+f"(c[0]), "+f"(c[1]), "+f"(c[2]), "+f"(c[3])
        : "r"(a[0]), "r"(a[1]), "r"(a[2]), "r"(a[3]), "r"(b[0]), "r"(b[1]));
}

DEVINL uint32_t pk2h(__half a, __half b) {
    __half2 t = __halves2half2(a, b);
    uint32_t u;
    memcpy(&u, &t, 4);
    return u;
}

// ---------------- convert: fp32 -> fp16 ----------------
DEVINL void cvt4(float4 v, __half* dst, int i) {
    uint2 u;
    u.x = pk2h(__float2half_rn(v.x), __float2half_rn(v.y));
    u.y = pk2h(__float2half_rn(v.z), __float2half_rn(v.w));
    reinterpret_cast<uint2*>(dst)[i] = u;
}

__global__ void convert_kernel(const float4* __restrict__ x,
                               const float4* __restrict__ wu,
                               const float4* __restrict__ wd) {
    const int X4  = M_TOK * K1 / 4;
    const int WU4 = N1 * K1 / 4;
    const int WD4 = N2 * K2 / 4;
    const int stride = gridDim.x * blockDim.x;
    const int t0 = blockIdx.x * blockDim.x + threadIdx.x;
    for (int i = t0; i < X4;  i += stride) cvt4(x[i],  g_x,  i);
    for (int i = t0; i < WU4; i += stride) cvt4(wu[i], g_wu, i);
    for (int i = t0; i < WD4; i += stride) cvt4(wd[i], g_wd, i);
}

// ---------------- tile loader (SW128 swizzle) ----------------
template <int ROWS>
DEVINL void load_tile(uint32_t sub, const __half* __restrict__ src,
                      int row0, int k0, int KDIM, int tid) {
    constexpr int ITERS = ROWS * 8 / 256;
#pragma unroll
    for (int j = 0; j < ITERS; j++) {
        const int idx = tid + j * 256;
        const int rr = idx >> 3;
        const int ss = idx & 7;
        const uint32_t off = (uint32_t)(rr * 128 + ss * 16);
        const uint32_t dst = sub + (off ^ ((off >> 3) & 0x70));
        cp16(dst, src + (size_t)(row0 + rr) * KDIM + (k0 + ss * 8));
    }
}

DEVINL void load_chunk(uint32_t sb, int k0, int tid,
                       const __half* A, const __half* B,
                       int m0, int n0, int KDIM) {
    load_tile<TM>(sb,          A, m0, k0, KDIM, tid);
    load_tile<TN>(sb + A_TILE, B, n0, k0, KDIM, tid);
    cp_commit();
}

// ---------------- per-chunk MMA (warp tile 64x32) ----------------
DEVINL void compute_chunk(uint32_t sb, int lane, int wm, int wn,
                          float (&acc)[4][4][4]) {
    const uint32_t subA = sb;
    const uint32_t subB = sb + A_TILE;

    const int a_r0 = wm * 64 + (lane & 7) + ((lane >> 3) & 1) * 8;   // + mb*16
    const int a_k8 = (lane >> 4);
    const int b_r0 = wn * 32 + (lane & 7) + (lane >> 4) * 8;         // + g*16
    const int b_k8 = (lane >> 3) & 1;

#pragma unroll
    for (int ks = 0; ks < KC / 16; ks++) {
        uint32_t a[4][4];
#pragma unroll
        for (int mb = 0; mb < 4; mb++) {
            const int r = a_r0 + mb * 16;
            const int kk = ks * 16 + a_k8 * 8;
            const uint32_t off = (uint32_t)(r * 128) + (((uint32_t)(kk * 2)) ^ (uint32_t)((r & 7) << 4));
            ldsm4(a[mb], subA + off);
        }
#pragma unroll
        for (int g = 0; g < 2; g++) {
            const int r = b_r0 + g * 16;
            const int kk = ks * 16 + b_k8 * 8;
            const uint32_t off = (uint32_t)(r * 128) + (((uint32_t)(kk * 2)) ^ (uint32_t)((r & 7) << 4));
            uint32_t b[4];
            ldsm4(b, subB + off);
#pragma unroll
            for (int h = 0; h < 2; h++)
#pragma unroll
                for (int mb = 0; mb < 4; mb++)
                    mma16816(acc[mb][g * 2 + h], a[mb], b + 2 * h);
        }
    }
}

// ---------------- GEMM kernels ----------------
// MODE 1: X * WupT, fused silu*mask -> h (fp16)
// MODE 2: h * WdnT -> out fp32
template <int MODE>
__global__ void __launch_bounds__(256, 2)
gemm_kernel(const float* __restrict__ mask, float* __restrict__ out) {
    constexpr int KDIM = (MODE == 1) ? K1 : K2;
    constexpr int NC = KDIM / KC;
    const __half* A = (MODE == 1) ? g_x  : g_h;
    const __half* B = (MODE == 1) ? g_wu : g_wd;

    extern __shared__ __align__(1024) uint8_t smem_raw[];
    const uint32_t base = (smem_u32(smem_raw) + 1023u) & ~1023u;

    const int tid = threadIdx.x;
    const int lane = tid & 31;
    const int wid = tid >> 5;
    const int wm = wid >> 2;          // 0..1  (64-row half)
    const int wn = wid & 3;           // 0..3  (32-col quarter)
    const int m0 = blockIdx.y * TM;
    const int n0 = blockIdx.x * TN;

    float acc[4][4][4];
#pragma unroll
    for (int i = 0; i < 4; i++)
#pragma unroll
        for (int j = 0; j < 4; j++)
#pragma unroll
            for (int q = 0; q < 4; q++) acc[i][j][q] = 0.f;

    // prologue: stages 0..1
    load_chunk(base,               0,  tid, A, B, m0, n0, KDIM);
    load_chunk(base + STAGE_BYTES, KC, tid, A, B, m0, n0, KDIM);

    for (int c = 0; c < NC; ++c) {
        if (c + 1 < NC) cp_wait<1>(); else cp_wait<0>();
        __syncthreads();   // chunk c resident; stage (c+2)%3 == (c-1)%3 is free

        if (c + 2 < NC)
            load_chunk(base + ((c + 2) % STAGES) * STAGE_BYTES, (c + 2) * KC,
                       tid, A, B, m0, n0, KDIM);

        compute_chunk(base + (c % STAGES) * STAGE_BYTES, lane, wm, wn, acc);
    }

    // ---------------- epilogue ----------------
    const int mw0 = m0 + wm * 64;
    const int nw0 = n0 + wn * 32;
#pragma unroll
    for (int mb = 0; mb < 4; mb++) {
        const int r0 = mw0 + mb * 16 + (lane >> 2);
        if (MODE == 1) {
            const int e = nw0 >> 6;   // expert constant across the 32-wide warp tile
            const float mk0 = mask[(size_t)r0 * NEXP + e];
            const float mk1 = mask[(size_t)(r0 + 8) * NEXP + e];
#pragma unroll
            for (int nb = 0; nb < 4; nb++) {
                const int col = nw0 + nb * 8 + (lane & 3) * 2;
                float v[4] = {acc[mb][nb][0], acc[mb][nb][1],
                              acc[mb][nb][2], acc[mb][nb][3]};
                float hv[4];
                hv[0] = v[0] * (1.f / (1.f + __expf(-v[0]))) * mk0;
                hv[1] = v[1] * (1.f / (1.f + __expf(-v[1]))) * mk0;
                hv[2] = v[2] * (1.f / (1.f + __expf(-v[2]))) * mk1;
                hv[3] = v[3] * (1.f / (1.f + __expf(-v[3]))) * mk1;
                *reinterpret_cast<uint32_t*>(g_h + (size_t)r0 * K2 + col) =
                    pk2h(__float2half_rn(hv[0]), __float2half_rn(hv[1]));
                *reinterpret_cast<uint32_t*>(g_h + (size_t)(r0 + 8) * K2 + col) =
                    pk2h(__float2half_rn(hv[2]), __float2half_rn(hv[3]));
            }
        } else {
#pragma unroll
            for (int nb = 0; nb < 4; nb++) {
                const int col = nw0 + nb * 8 + (lane & 3) * 2;
                *reinterpret_cast<float2*>(out + (size_t)r0 * N2 + col) =
                    make_float2(acc[mb][nb][0], acc[mb][nb][1]);
                *reinterpret_cast<float2*>(out + (size_t)(r0 + 8) * N2 + col) =
                    make_float2(acc[mb][nb][2], acc[mb][nb][3]);
            }
        }
    }
}

// ---------------- launch ----------------
extern "C" void kernel_launch(void* const* d_in, const int* in_sizes, int n_in,
                              void* d_out, int out_size) {
    const float* x    = (const float*)d_in[0];   // [8192, 2048]
    const float* mask = (const float*)d_in[1];   // [8192, 64]
    const float* wu   = (const float*)d_in[2];   // [4096, 2048]
    const float* wd   = (const float*)d_in[3];   // [2048, 4096]
    float* out = (float*)d_out;

    cudaFuncSetAttribute(gemm_kernel<1>, cudaFuncAttributeMaxDynamicSharedMemorySize, SMEM_BYTES);
    cudaFuncSetAttribute(gemm_kernel<2>, cudaFuncAttributeMaxDynamicSharedMemorySize, SMEM_BYTES);

    convert_kernel<<<1024, 256>>>((const float4*)x, (const float4*)wu, (const float4*)wd);
    gemm_kernel<1><<<dim3(N1 / TN, M_TOK / TM), 256, SMEM_BYTES>>>(mask, nullptr);
    gemm_kernel<2><<<dim3(N2 / TN, M_TOK / TM), 256, SMEM_BYTES>>>(nullptr, out);
}